// round 7
// baseline (speedup 1.0000x reference)
#include <cuda_runtime.h>
#include <cuda_bf16.h>
#include <cstdint>
#include <cstddef>

#define S_LEN  2048
#define DMODEL 1024
#define NHEAD  16
#define DK     64
#define NTOK   4096

// ===================== low-level helpers (base sm_103 target safe) =====================
__device__ __forceinline__ uint32_t smem_u32(const void* p) {
    uint32_t a;
    asm("{ .reg .u64 t; cvta.to.shared.u64 t, %1; cvt.u32.u64 %0, t; }" : "=r"(a) : "l"(p));
    return a;
}
#define CP16(dst, src) \
    asm volatile("cp.async.cg.shared.global [%0], [%1], 16;" :: "r"(dst), "l"(src))
#define CP_COMMIT() asm volatile("cp.async.commit_group;" ::: "memory")
#define CP_WAIT(n)  asm volatile("cp.async.wait_group %0;" :: "n"(n) : "memory")
#define LDSM4(d, addr) \
    asm volatile("ldmatrix.sync.aligned.m8n8.x4.shared.b16 {%0,%1,%2,%3}, [%4];" \
        : "=r"((d)[0]), "=r"((d)[1]), "=r"((d)[2]), "=r"((d)[3]) : "r"(addr))
#define MMA_BF16(c, a, b) \
    asm volatile("mma.sync.aligned.m16n8k16.row.col.f32.bf16.bf16.f32 " \
        "{%0,%1,%2,%3}, {%4,%5,%6,%7}, {%8,%9}, {%0,%1,%2,%3};" \
        : "+f"((c)[0]), "+f"((c)[1]), "+f"((c)[2]), "+f"((c)[3]) \
        : "r"((a)[0]), "r"((a)[1]), "r"((a)[2]), "r"((a)[3]), "r"((b)[0]), "r"((b)[1]))

__device__ __forceinline__ void split2(float v, __nv_bfloat16& h, __nv_bfloat16& l) {
    h = __float2bfloat16(v);
    l = __float2bfloat16(v - __bfloat162float(h));
}
__device__ __forceinline__ void split_pack(float x, float y, uint32_t& hp, uint32_t& lp) {
    __nv_bfloat16 hx, lx, hy, ly;
    split2(x, hx, lx); split2(y, hy, ly);
    __nv_bfloat162 h2(hx, hy), l2(lx, ly);
    hp = *reinterpret_cast<uint32_t*>(&h2);
    lp = *reinterpret_cast<uint32_t*>(&l2);
}

// ===================== scratch =====================
__device__ __nv_bfloat16 g_qh[NTOK*DMODEL], g_ql[NTOK*DMODEL];
__device__ __nv_bfloat16 g_kh[NTOK*DMODEL], g_kl[NTOK*DMODEL];
__device__ __nv_bfloat16 g_vh[NTOK*DMODEL], g_vl[NTOK*DMODEL];
__device__ __nv_bfloat16 g_Wqh[DMODEL*DMODEL], g_Wql[DMODEL*DMODEL];
__device__ __nv_bfloat16 g_Wkh[DMODEL*DMODEL], g_Wkl[DMODEL*DMODEL];
__device__ __nv_bfloat16 g_Wvh[DMODEL*DMODEL], g_Wvl[DMODEL*DMODEL];
__device__ __nv_bfloat16 g_Woh[DMODEL*DMODEL], g_Wol[DMODEL*DMODEL];
__device__ __nv_bfloat16 g_qph[NTOK*DMODEL], g_qpl[NTOK*DMODEL];
__device__ __nv_bfloat16 g_kph[NTOK*DMODEL], g_kpl[NTOK*DMODEL];
__device__ __nv_bfloat16 g_vTh[2*NHEAD*DK*S_LEN], g_vTl[2*NHEAD*DK*S_LEN];
__device__ __nv_bfloat16 g_ath[NTOK*DMODEL], g_atl[NTOK*DMODEL];

// ===================== merged fp32 -> (bf16 hi, bf16 lo) =====================
__global__ __launch_bounds__(256) void cvt_all(
    const float* __restrict__ q, const float* __restrict__ k, const float* __restrict__ v,
    const float* __restrict__ Wq, const float* __restrict__ Wk,
    const float* __restrict__ Wv, const float* __restrict__ Wo,
    __nv_bfloat16* qh, __nv_bfloat16* ql, __nv_bfloat16* kh, __nv_bfloat16* kl,
    __nv_bfloat16* vh, __nv_bfloat16* vl,
    __nv_bfloat16* Wqh, __nv_bfloat16* Wql, __nv_bfloat16* Wkh, __nv_bfloat16* Wkl,
    __nv_bfloat16* Wvh, __nv_bfloat16* Wvl, __nv_bfloat16* Woh, __nv_bfloat16* Wol)
{
    int bid = blockIdx.x;
    const float* src; __nv_bfloat16 *hi, *lo; int lb;
    if      (bid < 4096)  { src = q;  hi = qh;  lo = ql;  lb = bid; }
    else if (bid < 8192)  { src = k;  hi = kh;  lo = kl;  lb = bid - 4096; }
    else if (bid < 12288) { src = v;  hi = vh;  lo = vl;  lb = bid - 8192; }
    else if (bid < 13312) { src = Wq; hi = Wqh; lo = Wql; lb = bid - 12288; }
    else if (bid < 14336) { src = Wk; hi = Wkh; lo = Wkl; lb = bid - 13312; }
    else if (bid < 15360) { src = Wv; hi = Wvh; lo = Wvl; lb = bid - 14336; }
    else                  { src = Wo; hi = Woh; lo = Wol; lb = bid - 15360; }
    int i = (lb * 256 + threadIdx.x) * 4;
    float4 val = *(const float4*)(src + i);
    __nv_bfloat16 h0, h1, h2, h3, l0, l1, l2, l3;
    split2(val.x, h0, l0); split2(val.y, h1, l1);
    split2(val.z, h2, l2); split2(val.w, h3, l3);
    *(__nv_bfloat162*)(hi + i)     = __nv_bfloat162(h0, h1);
    *(__nv_bfloat162*)(hi + i + 2) = __nv_bfloat162(h2, h3);
    *(__nv_bfloat162*)(lo + i)     = __nv_bfloat162(l0, l1);
    *(__nv_bfloat162*)(lo + i + 2) = __nv_bfloat162(l2, l3);
}

// ===================== HMMA bf16x3 GEMM body (K=1024, 128x128 tile, 4 warps 64x64) =====================
// ep: 0 fp32+bias | 1 bf16 hi/lo (+bias)*scale | 3 bf16 hi/lo V-transposed
__device__ __forceinline__ void gemm_body(
    int ep,
    const char* Ah, const char* Al, const char* Bh, const char* Bl,
    float* C32, __nv_bfloat16* Chi, __nv_bfloat16* Clo,
    const float* bias, float scale, char* smem)
{
    constexpr int SA = 128 * 80;
    constexpr int SB = 128 * 80;
    constexpr int STAGE = 2 * SA + 2 * SB;
    const uint32_t sbase = smem_u32(smem);
    const int ldA = DMODEL, ldB = DMODEL, ldC = DMODEL;

    const int tid = threadIdx.x;
    const int warp = tid >> 5, lane = tid & 31;
    const int wm0 = (warp >> 1) * 64, wn0 = (warp & 1) * 64;
    const int m0 = blockIdx.y * 128;
    const int n0 = blockIdx.x * 128;

    float acc[4][8][4];
#pragma unroll
    for (int i = 0; i < 4; ++i)
#pragma unroll
        for (int j = 0; j < 8; ++j)
#pragma unroll
            for (int e = 0; e < 4; ++e) acc[i][j][e] = 0.f;

    auto load_chunk = [&](int c, int buf) {
        const uint32_t s = sbase + buf * STAGE;
        const long long kB = (long long)c * 64;
#pragma unroll 4
        for (int u = tid; u < 512; u += 128) {
            int r = u >> 2, cc = u & 3;
            long long go = ((long long)(m0 + r) * ldA) * 2 + kB + cc * 16;
            uint32_t so = r * 80 + cc * 16;
            CP16(s + so, Ah + go);
            CP16(s + SA + so, Al + go);
        }
#pragma unroll 4
        for (int u = tid; u < 512; u += 128) {
            int r = u >> 2, cc = u & 3;
            long long go = ((long long)(n0 + r) * ldB) * 2 + kB + cc * 16;
            uint32_t so = r * 80 + cc * 16;
            CP16(s + 2 * SA + so, Bh + go);
            CP16(s + 2 * SA + SB + so, Bl + go);
        }
        CP_COMMIT();
    };

    const uint32_t aAddr = (wm0 + (lane & 15)) * 80 + (lane >> 4) * 16;
    const int g = lane >> 3;
    const uint32_t bAddr = 2 * SA + (wn0 + (g >> 1) * 8 + (lane & 7)) * 80 + (g & 1) * 16;

    load_chunk(0, 0);

    const int chunks = 32;
    for (int c = 0; c < chunks; ++c) {
        const int buf = c & 1;
        if (c + 1 < chunks) {
            load_chunk(c + 1, buf ^ 1);
            CP_WAIT(1);
        } else {
            CP_WAIT(0);
        }
        __syncthreads();

        const uint32_t s = sbase + buf * STAGE;
#pragma unroll
        for (int ks = 0; ks < 2; ++ks) {
            const uint32_t kb = ks * 32;
            uint32_t ah[4][4], al[4][4];
#pragma unroll
            for (int mt = 0; mt < 4; ++mt) {
                LDSM4(ah[mt], s + aAddr + mt * 16 * 80 + kb);
                LDSM4(al[mt], s + SA + aAddr + mt * 16 * 80 + kb);
            }
            uint32_t bh[8][2], bl[8][2];
#pragma unroll
            for (int ntp = 0; ntp < 4; ++ntp) {
                uint32_t t[4];
                LDSM4(t, s + bAddr + ntp * 16 * 80 + kb);
                bh[ntp*2][0] = t[0]; bh[ntp*2][1] = t[1];
                bh[ntp*2+1][0] = t[2]; bh[ntp*2+1][1] = t[3];
                LDSM4(t, s + SB + bAddr + ntp * 16 * 80 + kb);
                bl[ntp*2][0] = t[0]; bl[ntp*2][1] = t[1];
                bl[ntp*2+1][0] = t[2]; bl[ntp*2+1][1] = t[3];
            }
            // product-major: same-acc reuse distance = 32 MMAs
#pragma unroll
            for (int mt = 0; mt < 4; ++mt)
#pragma unroll
                for (int nt = 0; nt < 8; ++nt)
                    MMA_BF16(acc[mt][nt], ah[mt], bh[nt]);
#pragma unroll
            for (int mt = 0; mt < 4; ++mt)
#pragma unroll
                for (int nt = 0; nt < 8; ++nt)
                    MMA_BF16(acc[mt][nt], ah[mt], bl[nt]);
#pragma unroll
            for (int mt = 0; mt < 4; ++mt)
#pragma unroll
                for (int nt = 0; nt < 8; ++nt)
                    MMA_BF16(acc[mt][nt], al[mt], bh[nt]);
        }
        __syncthreads();
    }

#pragma unroll
    for (int mt = 0; mt < 4; ++mt) {
#pragma unroll
        for (int nt = 0; nt < 8; ++nt) {
            int row0 = m0 + wm0 + mt * 16 + (lane >> 2);
            int row1 = row0 + 8;
            int col = n0 + wn0 + nt * 8 + (lane & 3) * 2;
            float p0 = acc[mt][nt][0], p1 = acc[mt][nt][1];
            float p2 = acc[mt][nt][2], p3 = acc[mt][nt][3];
            if (ep == 0) {
                float b0 = bias[col], b1 = bias[col + 1];
                *(float2*)&C32[(long long)row0 * ldC + col] = make_float2(p0 + b0, p1 + b1);
                *(float2*)&C32[(long long)row1 * ldC + col] = make_float2(p2 + b0, p3 + b1);
            } else if (ep == 1) {
                float b0 = bias[col], b1 = bias[col + 1];
                float v0 = (p0 + b0) * scale, v1 = (p1 + b1) * scale;
                float v2 = (p2 + b0) * scale, v3 = (p3 + b1) * scale;
                uint32_t hp, lp;
                split_pack(v0, v1, hp, lp);
                *(uint32_t*)&Chi[(long long)row0 * ldC + col] = hp;
                *(uint32_t*)&Clo[(long long)row0 * ldC + col] = lp;
                split_pack(v2, v3, hp, lp);
                *(uint32_t*)&Chi[(long long)row1 * ldC + col] = hp;
                *(uint32_t*)&Clo[(long long)row1 * ldC + col] = lp;
            } else {  // ep == 3 : per-head transposed V: [b][h][d][s]
                float vals[4] = { p0, p1, p2, p3 };
                int rows[4] = { row0, row0, row1, row1 };
                int cols[4] = { col, col + 1, col, col + 1 };
#pragma unroll
                for (int e = 0; e < 4; ++e) {
                    float vv = vals[e] + bias[cols[e]];
                    __nv_bfloat16 h, l; split2(vv, h, l);
                    int bidx = rows[e] >> 11, sidx = rows[e] & 2047;
                    int hd = cols[e] >> 6, d = cols[e] & 63;
                    long long dst = ((long long)bidx * NHEAD + hd) * (DK * S_LEN)
                                  + (long long)d * S_LEN + sidx;
                    Chi[dst] = h; Clo[dst] = l;
                }
            }
        }
    }
}

// merged Q/K/V projections: blockIdx.z selects operands
__global__ __launch_bounds__(128, 2) void proj_qkv(
    const __nv_bfloat16* qh, const __nv_bfloat16* ql,
    const __nv_bfloat16* kh, const __nv_bfloat16* kl,
    const __nv_bfloat16* vh, const __nv_bfloat16* vl,
    const __nv_bfloat16* Wqh, const __nv_bfloat16* Wql,
    const __nv_bfloat16* Wkh, const __nv_bfloat16* Wkl,
    const __nv_bfloat16* Wvh, const __nv_bfloat16* Wvl,
    const float* bq, const float* bk, const float* bv,
    __nv_bfloat16* qph, __nv_bfloat16* qpl,
    __nv_bfloat16* kph, __nv_bfloat16* kpl,
    __nv_bfloat16* vTh, __nv_bfloat16* vTl)
{
    extern __shared__ char smem[];
    int z = blockIdx.z;
    if (z == 0) {
        gemm_body(1, (const char*)qh, (const char*)ql, (const char*)Wqh, (const char*)Wql,
                  nullptr, qph, qpl, bq, 0.125f, smem);
    } else if (z == 1) {
        gemm_body(1, (const char*)kh, (const char*)kl, (const char*)Wkh, (const char*)Wkl,
                  nullptr, kph, kpl, bk, 1.0f, smem);
    } else {
        gemm_body(3, (const char*)vh, (const char*)vl, (const char*)Wvh, (const char*)Wvl,
                  nullptr, vTh, vTl, bv, 1.0f, smem);
    }
}

// final projection (fp32 out + bias)
__global__ __launch_bounds__(128, 2) void proj_out(
    const __nv_bfloat16* ath, const __nv_bfloat16* atl,
    const __nv_bfloat16* Woh, const __nv_bfloat16* Wol,
    const float* bo, float* out)
{
    extern __shared__ char smem[];
    gemm_body(0, (const char*)ath, (const char*)atl, (const char*)Woh, (const char*)Wol,
              out, nullptr, nullptr, bo, 1.0f, smem);
}

// ===================== fused flash attention v4 (4 warps, 64-key stages, 2 CTA/SM) =====================
#define FB_PITCH 144
#define FB_QSZ  (128 * FB_PITCH)             // 18432 per hi/lo
#define FB_KSZ  (64 * FB_PITCH)              // 9216 per hi/lo
#define FB_VSZ  (64 * FB_PITCH)              // 9216 per hi/lo
#define FB_QREG (2 * FB_QSZ)                 // 36864
#define FB_STAGE (2 * FB_KSZ + 2 * FB_VSZ)   // 36864
#define FB_SMEM  (FB_QREG + 2 * FB_STAGE)    // 110592

__global__ __launch_bounds__(128, 2) void flash_attn(
    const __nv_bfloat16* __restrict__ qh_, const __nv_bfloat16* __restrict__ ql_,
    const __nv_bfloat16* __restrict__ kh_, const __nv_bfloat16* __restrict__ kl_,
    const __nv_bfloat16* __restrict__ vth_, const __nv_bfloat16* __restrict__ vtl_,
    __nv_bfloat16* __restrict__ oh_, __nv_bfloat16* __restrict__ ol_)
{
    extern __shared__ char smem[];
    const uint32_t sb = smem_u32(smem);
    const int tid = threadIdx.x;
    const int warp = tid >> 5, lane = tid & 31;
    const int qt = blockIdx.x, h = blockIdx.y, b = blockIdx.z;

    const long long qrow0 = (long long)(b * S_LEN + qt * 128);
    const char* Qhg = (const char*)qh_ + (qrow0 * DMODEL + h * DK) * 2;
    const char* Qlg = (const char*)ql_ + (qrow0 * DMODEL + h * DK) * 2;
    const char* Khg = (const char*)kh_ + ((long long)b * S_LEN * DMODEL + h * DK) * 2;
    const char* Klg = (const char*)kl_ + ((long long)b * S_LEN * DMODEL + h * DK) * 2;
    const char* Vhg = (const char*)vth_ + ((long long)((b * NHEAD + h) * DK) * S_LEN) * 2;
    const char* Vlg = (const char*)vtl_ + ((long long)((b * NHEAD + h) * DK) * S_LEN) * 2;

    auto loadQ = [&]() {
#pragma unroll 8
        for (int u = tid; u < 1024; u += 128) {
            int r = u >> 3, seg = (u & 7) << 4;
            CP16(sb + r * FB_PITCH + seg, Qhg + (long long)r * 2048 + seg);
            CP16(sb + FB_QSZ + r * FB_PITCH + seg, Qlg + (long long)r * 2048 + seg);
        }
    };
    auto loadKV = [&](int kt, int buf) {   // kt indexes 64-key tiles
        const uint32_t s = sb + FB_QREG + buf * FB_STAGE;
        const char* kh = Khg + (long long)kt * 64 * 2048;
        const char* kl = Klg + (long long)kt * 64 * 2048;
#pragma unroll 4
        for (int u = tid; u < 512; u += 128) {
            int r = u >> 3, seg = (u & 7) << 4;
            CP16(s + r * FB_PITCH + seg, kh + (long long)r * 2048 + seg);
            CP16(s + FB_KSZ + r * FB_PITCH + seg, kl + (long long)r * 2048 + seg);
        }
        const char* vh = Vhg + kt * 128;
        const char* vl = Vlg + kt * 128;
#pragma unroll 4
        for (int u = tid; u < 512; u += 128) {
            int r = u >> 3, seg = (u & 7) << 4;
            CP16(s + 2 * FB_KSZ + r * FB_PITCH + seg, vh + (long long)r * 4096 + seg);
            CP16(s + 2 * FB_KSZ + FB_VSZ + r * FB_PITCH + seg, vl + (long long)r * 4096 + seg);
        }
    };

    float accO[2][8][4];
#pragma unroll
    for (int mt = 0; mt < 2; ++mt)
#pragma unroll
        for (int i = 0; i < 8; ++i)
#pragma unroll
            for (int e = 0; e < 4; ++e) accO[mt][i][e] = 0.f;
    float fm[2][2] = {{-1e30f, -1e30f}, {-1e30f, -1e30f}};
    float fl[2][2] = {{0.f, 0.f}, {0.f, 0.f}};
    uint32_t qfh[2][4][4];   // resident Q-hi frags

    loadQ(); loadKV(0, 0); CP_COMMIT();
    loadKV(1, 1); CP_COMMIT();

    const uint32_t qAddr = sb + (warp * 32 + (lane & 15)) * FB_PITCH + (lane >> 4) * 16;
    const int g = lane >> 3;
    const uint32_t bRow = (g >> 1) * 8 + (lane & 7);
    const uint32_t bHalf = (g & 1) * 16;

    const int NT64 = S_LEN / 64;   // 32
    for (int kt = 0; kt < NT64; ++kt) {
        CP_WAIT(1);
        __syncthreads();
        if (kt == 0) {
#pragma unroll
            for (int mt = 0; mt < 2; ++mt)
#pragma unroll
                for (int ks = 0; ks < 4; ++ks)
                    LDSM4(qfh[mt][ks], qAddr + mt * 16 * FB_PITCH + ks * 32);
        }
        const uint32_t s = sb + FB_QREG + (kt & 1) * FB_STAGE;

        // ---- S = Q @ K^T over 64 keys (3 products, product-major) ----
        float accS[2][8][4];
#pragma unroll
        for (int mt = 0; mt < 2; ++mt)
#pragma unroll
            for (int i = 0; i < 8; ++i)
#pragma unroll
                for (int e = 0; e < 4; ++e) accS[mt][i][e] = 0.f;
#pragma unroll
        for (int ks = 0; ks < 4; ++ks) {
            uint32_t qfl0[4], qfl1[4];
            LDSM4(qfl0, qAddr + FB_QSZ + 0 * 16 * FB_PITCH + ks * 32);
            LDSM4(qfl1, qAddr + FB_QSZ + 1 * 16 * FB_PITCH + ks * 32);
            uint32_t kf_h[4][4], kf_l[4][4];
#pragma unroll
            for (int ntp = 0; ntp < 4; ++ntp) {
                const uint32_t kA = s + (ntp * 16 + bRow) * FB_PITCH + bHalf + ks * 32;
                LDSM4(kf_h[ntp], kA);
                LDSM4(kf_l[ntp], kA + FB_KSZ);
            }
            // pass 1: Qhi * Khi (16 MMAs, distinct accumulators)
#pragma unroll
            for (int ntp = 0; ntp < 4; ++ntp) {
                uint32_t bh0[2] = { kf_h[ntp][0], kf_h[ntp][1] };
                uint32_t bh1[2] = { kf_h[ntp][2], kf_h[ntp][3] };
                MMA_BF16(accS[0][2*ntp],   qfh[0][ks], bh0);
                MMA_BF16(accS[0][2*ntp+1], qfh[0][ks], bh1);
                MMA_BF16(accS[1][2*ntp],   qfh[1][ks], bh0);
                MMA_BF16(accS[1][2*ntp+1], qfh[1][ks], bh1);
            }
            // pass 2: Qhi * Klo
#pragma unroll
            for (int ntp = 0; ntp < 4; ++ntp) {
                uint32_t bl0[2] = { kf_l[ntp][0], kf_l[ntp][1] };
                uint32_t bl1[2] = { kf_l[ntp][2], kf_l[ntp][3] };
                MMA_BF16(accS[0][2*ntp],   qfh[0][ks], bl0);
                MMA_BF16(accS[0][2*ntp+1], qfh[0][ks], bl1);
                MMA_BF16(accS[1][2*ntp],   qfh[1][ks], bl0);
                MMA_BF16(accS[1][2*ntp+1], qfh[1][ks], bl1);
            }
            // pass 3: Qlo * Khi
#pragma unroll
            for (int ntp = 0; ntp < 4; ++ntp) {
                uint32_t bh0[2] = { kf_h[ntp][0], kf_h[ntp][1] };
                uint32_t bh1[2] = { kf_h[ntp][2], kf_h[ntp][3] };
                MMA_BF16(accS[0][2*ntp],   qfl0, bh0);
                MMA_BF16(accS[0][2*ntp+1], qfl0, bh1);
                MMA_BF16(accS[1][2*ntp],   qfl1, bh0);
                MMA_BF16(accS[1][2*ntp+1], qfl1, bh1);
            }
        }

        // ---- online softmax ----
#pragma unroll
        for (int mt = 0; mt < 2; ++mt) {
            float mx0 = -1e30f, mx1 = -1e30f;
#pragma unroll
            for (int nt = 0; nt < 8; ++nt) {
                mx0 = fmaxf(mx0, fmaxf(accS[mt][nt][0], accS[mt][nt][1]));
                mx1 = fmaxf(mx1, fmaxf(accS[mt][nt][2], accS[mt][nt][3]));
            }
            mx0 = fmaxf(mx0, __shfl_xor_sync(0xffffffffu, mx0, 1));
            mx0 = fmaxf(mx0, __shfl_xor_sync(0xffffffffu, mx0, 2));
            mx1 = fmaxf(mx1, __shfl_xor_sync(0xffffffffu, mx1, 1));
            mx1 = fmaxf(mx1, __shfl_xor_sync(0xffffffffu, mx1, 2));
            float mn0 = fmaxf(fm[mt][0], mx0), mn1 = fmaxf(fm[mt][1], mx1);
            float c0 = __expf(fm[mt][0] - mn0), c1 = __expf(fm[mt][1] - mn1);
            fm[mt][0] = mn0; fm[mt][1] = mn1;
            float s0 = 0.f, s1 = 0.f;
#pragma unroll
            for (int nt = 0; nt < 8; ++nt) {
                accS[mt][nt][0] = __expf(accS[mt][nt][0] - mn0);
                accS[mt][nt][1] = __expf(accS[mt][nt][1] - mn0);
                accS[mt][nt][2] = __expf(accS[mt][nt][2] - mn1);
                accS[mt][nt][3] = __expf(accS[mt][nt][3] - mn1);
                s0 += accS[mt][nt][0] + accS[mt][nt][1];
                s1 += accS[mt][nt][2] + accS[mt][nt][3];
            }
            s0 += __shfl_xor_sync(0xffffffffu, s0, 1);
            s0 += __shfl_xor_sync(0xffffffffu, s0, 2);
            s1 += __shfl_xor_sync(0xffffffffu, s1, 1);
            s1 += __shfl_xor_sync(0xffffffffu, s1, 2);
            fl[mt][0] = fl[mt][0] * c0 + s0;
            fl[mt][1] = fl[mt][1] * c1 + s1;
#pragma unroll
            for (int nt = 0; nt < 8; ++nt) {
                accO[mt][nt][0] *= c0; accO[mt][nt][1] *= c0;
                accO[mt][nt][2] *= c1; accO[mt][nt][3] *= c1;
            }
        }

        // ---- O += P @ V (3 products, product-major per kg) ----
#pragma unroll
        for (int kg = 0; kg < 4; ++kg) {
            uint32_t pah[2][4], pal[2][4];
#pragma unroll
            for (int mt = 0; mt < 2; ++mt) {
                split_pack(accS[mt][2*kg][0],   accS[mt][2*kg][1],   pah[mt][0], pal[mt][0]);
                split_pack(accS[mt][2*kg][2],   accS[mt][2*kg][3],   pah[mt][1], pal[mt][1]);
                split_pack(accS[mt][2*kg+1][0], accS[mt][2*kg+1][1], pah[mt][2], pal[mt][2]);
                split_pack(accS[mt][2*kg+1][2], accS[mt][2*kg+1][3], pah[mt][3], pal[mt][3]);
            }
            uint32_t vf_h[4][4], vf_l[4][4];
#pragma unroll
            for (int ntp = 0; ntp < 4; ++ntp) {
                const uint32_t vA = s + 2 * FB_KSZ + (ntp * 16 + bRow) * FB_PITCH
                                  + bHalf + kg * 32;
                LDSM4(vf_h[ntp], vA);
                LDSM4(vf_l[ntp], vA + FB_VSZ);
            }
            // pass 1: Phi * Vhi
#pragma unroll
            for (int ntp = 0; ntp < 4; ++ntp) {
                uint32_t bh0[2] = { vf_h[ntp][0], vf_h[ntp][1] };
                uint32_t bh1[2] = { vf_h[ntp][2], vf_h[ntp][3] };
                MMA_BF16(accO[0][2*ntp],   pah[0], bh0);
                MMA_BF16(accO[0][2*ntp+1], pah[0], bh1);
                MMA_BF16(accO[1][2*ntp],   pah[1], bh0);
                MMA_BF16(accO[1][2*ntp+1], pah[1], bh1);
            }
            // pass 2: Phi * Vlo
#pragma unroll
            for (int ntp = 0; ntp < 4; ++ntp) {
                uint32_t bl0[2] = { vf_l[ntp][0], vf_l[ntp][1] };
                uint32_t bl1[2] = { vf_l[ntp][2], vf_l[ntp][3] };
                MMA_BF16(accO[0][2*ntp],   pah[0], bl0);
                MMA_BF16(accO[0][2*ntp+1], pah[0], bl1);
                MMA_BF16(accO[1][2*ntp],   pah[1], bl0);
                MMA_BF16(accO[1][2*ntp+1], pah[1], bl1);
            }
            // pass 3: Plo * Vhi
#pragma unroll
            for (int ntp = 0; ntp < 4; ++ntp) {
                uint32_t bh0[2] = { vf_h[ntp][0], vf_h[ntp][1] };
                uint32_t bh1[2] = { vf_h[ntp][2], vf_h[ntp][3] };
                MMA_BF16(accO[0][2*ntp],   pal[0], bh0);
                MMA_BF16(accO[0][2*ntp+1], pal[0], bh1);
                MMA_BF16(accO[1][2*ntp],   pal[1], bh0);
                MMA_BF16(accO[1][2*ntp+1], pal[1], bh1);
            }
        }
        __syncthreads();
        if (kt + 2 < NT64) loadKV(kt + 2, kt & 1);
        CP_COMMIT();
    }

    // ---- epilogue ----
#pragma unroll
    for (int mt = 0; mt < 2; ++mt) {
        const float inv0 = 1.0f / fl[mt][0], inv1 = 1.0f / fl[mt][1];
        const long long tok0 = qrow0 + warp * 32 + mt * 16 + (lane >> 2);
        const int colb = h * DK + (lane & 3) * 2;
#pragma unroll
        for (int nt = 0; nt < 8; ++nt) {
            int col = colb + nt * 8;
            uint32_t hp, lp;
            split_pack(accO[mt][nt][0] * inv0, accO[mt][nt][1] * inv0, hp, lp);
            *(uint32_t*)&oh_[tok0 * DMODEL + col] = hp;
            *(uint32_t*)&ol_[tok0 * DMODEL + col] = lp;
            split_pack(accO[mt][nt][2] * inv1, accO[mt][nt][3] * inv1, hp, lp);
            *(uint32_t*)&oh_[(tok0 + 8) * DMODEL + col] = hp;
            *(uint32_t*)&ol_[(tok0 + 8) * DMODEL + col] = lp;
        }
    }
}

// ===================== host =====================
static inline void* sym(const void* s) { void* p; cudaGetSymbolAddress(&p, s); return p; }

extern "C" void kernel_launch(void* const* d_in, const int* in_sizes, int n_in,
                              void* d_out, int out_size) {
    const float* v  = (const float*)d_in[0];
    const float* k  = (const float*)d_in[1];
    const float* q  = (const float*)d_in[2];
    const float* Wv = (const float*)d_in[3];
    const float* bv = (const float*)d_in[4];
    const float* Wk = (const float*)d_in[5];
    const float* bk = (const float*)d_in[6];
    const float* Wq = (const float*)d_in[7];
    const float* bq = (const float*)d_in[8];
    const float* Wo = (const float*)d_in[9];
    const float* bo = (const float*)d_in[10];

    __nv_bfloat16 *qh=(__nv_bfloat16*)sym(g_qh), *ql=(__nv_bfloat16*)sym(g_ql);
    __nv_bfloat16 *kh=(__nv_bfloat16*)sym(g_kh), *kl=(__nv_bfloat16*)sym(g_kl);
    __nv_bfloat16 *vh=(__nv_bfloat16*)sym(g_vh), *vl=(__nv_bfloat16*)sym(g_vl);
    __nv_bfloat16 *Wqh=(__nv_bfloat16*)sym(g_Wqh), *Wql=(__nv_bfloat16*)sym(g_Wql);
    __nv_bfloat16 *Wkh=(__nv_bfloat16*)sym(g_Wkh), *Wkl=(__nv_bfloat16*)sym(g_Wkl);
    __nv_bfloat16 *Wvh=(__nv_bfloat16*)sym(g_Wvh), *Wvl=(__nv_bfloat16*)sym(g_Wvl);
    __nv_bfloat16 *Woh=(__nv_bfloat16*)sym(g_Woh), *Wol=(__nv_bfloat16*)sym(g_Wol);
    __nv_bfloat16 *qph=(__nv_bfloat16*)sym(g_qph), *qpl=(__nv_bfloat16*)sym(g_qpl);
    __nv_bfloat16 *kph=(__nv_bfloat16*)sym(g_kph), *kpl=(__nv_bfloat16*)sym(g_kpl);
    __nv_bfloat16 *vTh=(__nv_bfloat16*)sym(g_vTh), *vTl=(__nv_bfloat16*)sym(g_vTl);
    __nv_bfloat16 *ath=(__nv_bfloat16*)sym(g_ath), *atl=(__nv_bfloat16*)sym(g_atl);

    const int SM_G = 2 * (128 + 128) * 160;   // 81920
    cudaFuncSetAttribute(proj_qkv, cudaFuncAttributeMaxDynamicSharedMemorySize, SM_G);
    cudaFuncSetAttribute(proj_out, cudaFuncAttributeMaxDynamicSharedMemorySize, SM_G);
    cudaFuncSetAttribute(flash_attn, cudaFuncAttributeMaxDynamicSharedMemorySize, FB_SMEM);

    // launch 0: merged hi/lo splits
    cvt_all<<<16384, 256>>>(q, k, v, Wq, Wk, Wv, Wo,
                            qh, ql, kh, kl, vh, vl,
                            Wqh, Wql, Wkh, Wkl, Wvh, Wvl, Woh, Wol);

    // launch 1: merged Q/K/V projections
    proj_qkv<<<dim3(8, 32, 3), 128, SM_G>>>(
        qh, ql, kh, kl, vh, vl,
        Wqh, Wql, Wkh, Wkl, Wvh, Wvl,
        bq, bk, bv, qph, qpl, kph, kpl, vTh, vTl);

    // launch 2: fused flash attention (2 CTA/SM)
    flash_attn<<<dim3(S_LEN / 128, NHEAD, 2), 128, FB_SMEM>>>(
        qph, qpl, kph, kpl, vTh, vTl, ath, atl);

    // launch 3: final projection
    proj_out<<<dim3(8, 32), 128, SM_G>>>(ath, atl, Woh, Wol, bo, (float*)d_out);
}